// round 1
// baseline (speedup 1.0000x reference)
#include <cuda_runtime.h>
#include <stdint.h>

// PNLoss: prototypical-network leave-one-out loss.
// S=8192 support, N=2048 queries, D=128, C=256 classes.
// Inputs (metadata order): xq[N,D] f32, yq[N] int, xs[S,D] f32, ys[S] int, pos[N] int.
// Output: scalar f32 loss.
//
// Algebra: logit[n,c] = -0.5 * ( q2 - 2*(s - d*q2)/den + (m2 - d*(2s - q2))/den^2 )
//   where s = xq[n].mus[c], q2=||xq[n]||^2, m2=||mus[c]||^2, d=[c==y_n],
//   den = count[c]-d (clipped at 0.1), masked to 0 when den<=0.1.
// loss = mean_n( logsumexp_c(logit) - logit[n, y_n] ).

#define S_MAX 8192
#define N_MAX 2048
#define DIM   128
#define NC    256
#define CAP   40     // per-class member capacity (actual is exactly 32)
#define QB    16     // queries per block in K2

// --- scratch (no allocations allowed) ---
__device__ int   g_ys32[S_MAX];
__device__ int   g_pos32[N_MAX];
__device__ int   g_members[NC * CAP];
__device__ int   g_cnt[NC];
__device__ float g_cntf[NC];
// swizzled prototype sums: element (c, 4k+j) at [(k*NC + c)*4 + j]
__device__ float g_mus_sw[DIM / 4 * NC * 4];
__device__ float g_m2[NC];

// ---------------------------------------------------------------------------
// K0: dtype detection (int32 vs int64 index arrays), normalization to int32,
//     per-class member list build, output zeroing. Single block.
// ---------------------------------------------------------------------------
__global__ void k0_prepare(const void* __restrict__ ys_raw,
                           const void* __restrict__ pos_raw,
                           float* out, int S, int N)
{
    __shared__ int s_ys64, s_pos64;
    __shared__ int scnt[NC];
    int t = threadIdx.x;
    if (t == 0) { s_ys64 = 1; s_pos64 = 1; out[0] = 0.0f; }
    for (int i = t; i < NC; i += blockDim.x) scnt[i] = 0;
    __syncthreads();

    // If data is really int32, the int64 interpretation combines adjacent
    // values -> huge numbers. 64 samples => misdetection prob ~0.
    if (t < 64) {
        long long v = ((const long long*)ys_raw)[t];
        if (v < 0 || v >= NC) s_ys64 = 0;
        long long p = ((const long long*)pos_raw)[t];
        if (p < 0 || p >= S) s_pos64 = 0;
    }
    __syncthreads();
    const int ys64 = s_ys64, pos64 = s_pos64;

    for (int i = t; i < S; i += blockDim.x) {
        int v = ys64 ? (int)((const long long*)ys_raw)[i]
                     : ((const int*)ys_raw)[i];
        g_ys32[i] = v;
    }
    for (int i = t; i < N; i += blockDim.x) {
        int v = pos64 ? (int)((const long long*)pos_raw)[i]
                      : ((const int*)pos_raw)[i];
        g_pos32[i] = v;
    }
    __syncthreads();   // global writes by block visible to block

    for (int i = t; i < S; i += blockDim.x) {
        int c = g_ys32[i];
        if (c >= 0 && c < NC) {
            int slot = atomicAdd(&scnt[c], 1);
            if (slot < CAP) g_members[c * CAP + slot] = i;
        }
    }
    __syncthreads();
    for (int i = t; i < NC; i += blockDim.x) {
        g_cnt[i]  = scnt[i];
        g_cntf[i] = (float)scnt[i];
    }
}

// ---------------------------------------------------------------------------
// K1: per-class prototype sums + ||mus||^2. One block per class, 128 threads
//     (thread = dim). Writes mus in swizzled layout for K2 coalesced loads.
// ---------------------------------------------------------------------------
__global__ void k1_protos(const float* __restrict__ xs)
{
    int c = blockIdx.x;
    int t = threadIdx.x;           // dim index 0..127
    int cnt = g_cnt[c]; if (cnt > CAP) cnt = CAP;

    float acc = 0.0f;
    for (int j = 0; j < cnt; j++) {
        int s = g_members[c * CAP + j];
        acc += xs[(size_t)s * DIM + t];    // coalesced: 512B row per class member
    }
    // swizzled store: (c, t) -> [((t>>2)*NC + c)*4 + (t&3)]
    g_mus_sw[(((t >> 2) * NC) + c) * 4 + (t & 3)] = acc;

    float a2 = acc * acc;
    #pragma unroll
    for (int o = 16; o > 0; o >>= 1) a2 += __shfl_xor_sync(0xffffffffu, a2, o);
    __shared__ float wsum[4];
    if ((t & 31) == 0) wsum[t >> 5] = a2;
    __syncthreads();
    if (t == 0) g_m2[c] = wsum[0] + wsum[1] + wsum[2] + wsum[3];
}

// ---------------------------------------------------------------------------
// K2: logits + logsumexp + loss. 256 threads (thread = class), QB=16 queries
//     per block. mu row kept in registers (fully unrolled), xq staged
//     transposed in shared so one LDS.128 broadcast feeds 4 FFMAs.
// ---------------------------------------------------------------------------
__global__ void __launch_bounds__(256, 1)
k2_loss(const float* __restrict__ xq, float* out, int N)
{
    __shared__ __align__(16) float xqT[DIM][20];   // [d][q], padded to 20 for 16B align
    __shared__ float logits[QB * NC];
    __shared__ float q2s[QB];
    __shared__ int   ycls[QB];
    __shared__ float part[QB];

    const int tid   = threadIdx.x;
    const int qbase = blockIdx.x * QB;

    // stage xq transposed (coalesced global reads)
    for (int idx = tid; idx < QB * DIM; idx += 256) {
        int q = idx >> 7, d = idx & 127;
        int n = qbase + q;
        xqT[d][q] = (n < N) ? xq[(size_t)n * DIM + d] : 0.0f;
    }
    if (tid < QB) {
        int n = qbase + tid;
        ycls[tid] = (n < N) ? g_ys32[g_pos32[n]] : 0;
        part[tid] = 0.0f;
    }
    __syncthreads();

    // per-query squared norms (tiny; overlaps with mu LDGs below)
    if (tid < QB) {
        float s = 0.0f;
        #pragma unroll 8
        for (int d = 0; d < DIM; d++) { float v = xqT[d][tid]; s += v * v; }
        q2s[tid] = s;
    }

    // load this thread's class prototype row into registers (coalesced LDG.128)
    const int c = tid;
    float mu[DIM];
    #pragma unroll
    for (int k = 0; k < DIM / 4; k++) {
        float4 v = reinterpret_cast<const float4*>(g_mus_sw)[k * NC + c];
        mu[4 * k + 0] = v.x; mu[4 * k + 1] = v.y;
        mu[4 * k + 2] = v.z; mu[4 * k + 3] = v.w;
    }
    const float cntc = g_cntf[c];
    const float m2c  = g_m2[c];
    __syncthreads();   // q2s / ycls ready

    // main GEMM-ish phase: 4 queries at a time
    for (int qg = 0; qg < QB / 4; qg++) {
        float a0 = 0.f, a1 = 0.f, a2 = 0.f, a3 = 0.f;
        #pragma unroll
        for (int d = 0; d < DIM; d++) {
            float4 xv = *reinterpret_cast<const float4*>(&xqT[d][qg * 4]); // broadcast
            a0 = fmaf(mu[d], xv.x, a0);
            a1 = fmaf(mu[d], xv.y, a1);
            a2 = fmaf(mu[d], xv.z, a2);
            a3 = fmaf(mu[d], xv.w, a3);
        }
        float accs[4] = {a0, a1, a2, a3};
        #pragma unroll
        for (int j = 0; j < 4; j++) {
            int   q   = qg * 4 + j;
            float s   = accs[j];
            float q2  = q2s[q];
            float del = (c == ycls[q]) ? 1.0f : 0.0f;
            float dd  = cntc - del;
            float den = fmaxf(dd, 0.1f);
            float sp  = s - del * q2;
            float m2p = m2c - del * (2.0f * s - q2);
            float inv = 1.0f / den;
            float dist = q2 - 2.0f * sp * inv + m2p * inv * inv;
            logits[q * NC + c] = (dd > 0.1f) ? (-0.5f * dist) : 0.0f;
        }
    }
    __syncthreads();

    // logsumexp: warp w handles queries 2w, 2w+1 (8 classes per lane)
    const int w = tid >> 5, lane = tid & 31;
    for (int qi = 0; qi < 2; qi++) {
        int q = w * 2 + qi;
        int n = qbase + q;
        float v[8];
        float m = -1e30f;
        #pragma unroll
        for (int k = 0; k < 8; k++) {
            v[k] = logits[q * NC + lane + 32 * k];
            m = fmaxf(m, v[k]);
        }
        #pragma unroll
        for (int o = 16; o > 0; o >>= 1) m = fmaxf(m, __shfl_xor_sync(0xffffffffu, m, o));
        float sum = 0.0f;
        #pragma unroll
        for (int k = 0; k < 8; k++) sum += __expf(v[k] - m);
        #pragma unroll
        for (int o = 16; o > 0; o >>= 1) sum += __shfl_xor_sync(0xffffffffu, sum, o);
        if (lane == 0 && n < N) {
            float lse = m + __logf(sum);
            float ly  = logits[q * NC + ycls[q]];
            part[q] = lse - ly;
        }
    }
    __syncthreads();
    if (tid == 0) {
        float tot = 0.0f;
        #pragma unroll
        for (int q = 0; q < QB; q++) tot += part[q];
        atomicAdd(out, tot * (1.0f / (float)N));
    }
}

// ---------------------------------------------------------------------------
extern "C" void kernel_launch(void* const* d_in, const int* in_sizes, int n_in,
                              void* d_out, int out_size)
{
    const float* xq  = (const float*)d_in[0];
    // d_in[1] = yq (unused; yq == ys[pos] by construction)
    const float* xs  = (const float*)d_in[2];
    const void*  ys  = d_in[3];
    const void*  pos = d_in[4];
    float* out = (float*)d_out;

    int N = in_sizes[1];               // query count
    int S = in_sizes[3];               // support count
    if (N > N_MAX) N = N_MAX;
    if (S > S_MAX) S = S_MAX;

    k0_prepare<<<1, 256>>>(ys, pos, out, S, N);
    k1_protos<<<NC, DIM>>>(xs);
    int nblk = (N + QB - 1) / QB;
    k2_loss<<<nblk, 256>>>(xq, out, N);
}

// round 3
// speedup vs baseline: 1.3868x; 1.3868x over previous
#include <cuda_runtime.h>
#include <stdint.h>

// PNLoss: prototypical-network leave-one-out loss.
// S=8192 support, N=2048 queries, D=128, C=256 classes (exactly 32 members each).
// Inputs (metadata order): xq[N,D] f32, yq[N] int, xs[S,D] f32, ys[S] int, pos[N] int.
// Output: scalar f32 loss.
//
// logit[n,c] = -0.5*( q2 - 2*(s - d*q2)/den + (m2 - d*(2s - q2))/den^2 ),
//   s = xq[n].mus[c], q2=||xq||^2, m2=||mus[c]||^2, d=[c==y_n], den=max(cnt-d,0.1),
//   masked to 0 when cnt-d<=0.1.  loss = mean_n( lse_c(logit) - logit[n,y_n] ).

#define S_MAX 8192
#define N_MAX 2048
#define DIM   128
#define NC    256
#define CAP   40
#define QB    16

__device__ int   g_ys32[S_MAX];
__device__ int   g_pos32[N_MAX];
__device__ int   g_members[NC * CAP];
__device__ int   g_cnt[NC];
__device__ float g_cntf[NC];
__device__ float g_mus_sw[DIM / 4 * NC * 4];   // (c, 4k+j) at [(k*NC+c)*4+j]
__device__ float g_m2[NC];

// ---------------------------------------------------------------------------
// k_zero: reset counters + output (must precede k_build's atomics).
// ---------------------------------------------------------------------------
__global__ void k_zero(float* out)
{
    g_cnt[threadIdx.x] = 0;
    if (threadIdx.x == 0) out[0] = 0.0f;
}

// ---------------------------------------------------------------------------
// k_build: dtype detection, int normalization, member scatter. 64x128 = 8192
// threads, one support element each (grid-stride for safety).
// ---------------------------------------------------------------------------
__global__ void k_build(const void* __restrict__ ys_raw,
                        const void* __restrict__ pos_raw,
                        int S, int N)
{
    __shared__ int s_ys64, s_pos64;
    int t = threadIdx.x;
    if (t == 0) { s_ys64 = 1; s_pos64 = 1; }
    __syncthreads();
    // int32 data read as int64 packs two values -> out-of-range w.h.p.
    if (t < 64 && t < S && t < N) {
        long long v = ((const long long*)ys_raw)[t];
        if (v < 0 || v >= NC) s_ys64 = 0;
        long long p = ((const long long*)pos_raw)[t];
        if (p < 0 || p >= S) s_pos64 = 0;
    }
    __syncthreads();
    const int ys64 = s_ys64, pos64 = s_pos64;

    int stride = gridDim.x * blockDim.x;
    for (int i = blockIdx.x * blockDim.x + t; i < S; i += stride) {
        int v = ys64 ? (int)((const long long*)ys_raw)[i]
                     : ((const int*)ys_raw)[i];
        g_ys32[i] = v;
        if (v >= 0 && v < NC) {
            int slot = atomicAdd(&g_cnt[v], 1);
            if (slot < CAP) g_members[v * CAP + slot] = i;
        }
    }
    for (int i = blockIdx.x * blockDim.x + t; i < N; i += stride) {
        int v = pos64 ? (int)((const long long*)pos_raw)[i]
                      : ((const int*)pos_raw)[i];
        g_pos32[i] = v;
    }
}

// ---------------------------------------------------------------------------
// k1_protos: per-class prototype sums + ||mus||^2. Block = class, 128 thr
// (thread = dim). Warp 0 bitonic-sorts the member list first so summation
// order is canonical (atomic slot order varies across replays).
// ---------------------------------------------------------------------------
__global__ void k1_protos(const float* __restrict__ xs)
{
    __shared__ int   s_mem[CAP];
    __shared__ float wsum[4];
    int c = blockIdx.x;
    int t = threadIdx.x;
    int cnt = g_cnt[c]; if (cnt > CAP) cnt = CAP;

    if (t < 32) {
        int v = (t < cnt) ? g_members[c * CAP + t] : 0x7fffffff;
        if (cnt <= 32) {
            #pragma unroll
            for (int k = 2; k <= 32; k <<= 1) {
                #pragma unroll
                for (int j = k >> 1; j > 0; j >>= 1) {
                    int other = __shfl_xor_sync(0xffffffffu, v, j);
                    bool up   = ((t & k) == 0);
                    bool low  = ((t & j) == 0);
                    bool keepMin = (low == up);
                    int mn = min(v, other), mx = max(v, other);
                    v = keepMin ? mn : mx;
                }
            }
        }
        s_mem[t] = v;
    } else if (t >= 96 && t - 96 < CAP - 32) {
        // degenerate overflow case (never hit with 32-member classes)
        int j = 32 + (t - 96);
        s_mem[j] = (j < cnt) ? g_members[c * CAP + j] : 0x7fffffff;
    }
    __syncthreads();

    float acc = 0.0f;
    int j = 0;
    for (; j + 4 <= cnt; j += 4) {
        int s0 = s_mem[j], s1 = s_mem[j+1], s2 = s_mem[j+2], s3 = s_mem[j+3];
        float v0 = xs[(size_t)s0 * DIM + t];
        float v1 = xs[(size_t)s1 * DIM + t];
        float v2 = xs[(size_t)s2 * DIM + t];
        float v3 = xs[(size_t)s3 * DIM + t];
        acc += v0; acc += v1; acc += v2; acc += v3;
    }
    for (; j < cnt; j++) acc += xs[(size_t)s_mem[j] * DIM + t];

    g_mus_sw[(((t >> 2) * NC) + c) * 4 + (t & 3)] = acc;

    float a2 = acc * acc;
    #pragma unroll
    for (int o = 16; o > 0; o >>= 1) a2 += __shfl_xor_sync(0xffffffffu, a2, o);
    if ((t & 31) == 0) wsum[t >> 5] = a2;
    __syncthreads();
    if (t == 0) {
        g_m2[c]   = wsum[0] + wsum[1] + wsum[2] + wsum[3];
        g_cntf[c] = (float)g_cnt[c];
    }
}

// ---------------------------------------------------------------------------
// k2_loss: logits + logsumexp + loss. 256 thr (thread = class), QB queries
// per block; mu row in registers, xq transposed in shared (LDS.128 broadcast
// feeds 4 FFMAs).
// ---------------------------------------------------------------------------
__global__ void __launch_bounds__(256, 1)
k2_loss(const float* __restrict__ xq, float* out, int N)
{
    __shared__ __align__(16) float xqT[DIM][20];
    __shared__ float logits[QB * NC];
    __shared__ float q2s[QB];
    __shared__ int   ycls[QB];
    __shared__ float part[QB];

    const int tid   = threadIdx.x;
    const int qbase = blockIdx.x * QB;

    for (int idx = tid; idx < QB * DIM; idx += 256) {
        int q = idx >> 7, d = idx & 127;
        int n = qbase + q;
        xqT[d][q] = (n < N) ? xq[(size_t)n * DIM + d] : 0.0f;
    }
    if (tid < QB) {
        int n = qbase + tid;
        ycls[tid] = (n < N) ? g_ys32[g_pos32[n]] : 0;
        part[tid] = 0.0f;
    }
    __syncthreads();

    if (tid < QB) {
        float s = 0.0f;
        #pragma unroll 8
        for (int d = 0; d < DIM; d++) { float v = xqT[d][tid]; s += v * v; }
        q2s[tid] = s;
    }

    const int c = tid;
    float mu[DIM];
    #pragma unroll
    for (int k = 0; k < DIM / 4; k++) {
        float4 v = reinterpret_cast<const float4*>(g_mus_sw)[k * NC + c];
        mu[4*k+0] = v.x; mu[4*k+1] = v.y; mu[4*k+2] = v.z; mu[4*k+3] = v.w;
    }
    const float cntc = g_cntf[c];
    const float m2c  = g_m2[c];
    __syncthreads();

    for (int qg = 0; qg < QB / 4; qg++) {
        float a0 = 0.f, a1 = 0.f, a2 = 0.f, a3 = 0.f;
        #pragma unroll
        for (int d = 0; d < DIM; d++) {
            float4 xv = *reinterpret_cast<const float4*>(&xqT[d][qg * 4]);
            a0 = fmaf(mu[d], xv.x, a0);
            a1 = fmaf(mu[d], xv.y, a1);
            a2 = fmaf(mu[d], xv.z, a2);
            a3 = fmaf(mu[d], xv.w, a3);
        }
        float accs[4] = {a0, a1, a2, a3};
        #pragma unroll
        for (int j = 0; j < 4; j++) {
            int   q   = qg * 4 + j;
            float s   = accs[j];
            float q2  = q2s[q];
            float del = (c == ycls[q]) ? 1.0f : 0.0f;
            float dd  = cntc - del;
            float den = fmaxf(dd, 0.1f);
            float sp  = s - del * q2;
            float m2p = m2c - del * (2.0f * s - q2);
            float inv = 1.0f / den;
            float dist = q2 - 2.0f * sp * inv + m2p * inv * inv;
            logits[q * NC + c] = (dd > 0.1f) ? (-0.5f * dist) : 0.0f;
        }
    }
    __syncthreads();

    const int w = tid >> 5, lane = tid & 31;
    for (int qi = 0; qi < 2; qi++) {
        int q = w * 2 + qi;
        int n = qbase + q;
        float v[8];
        float m = -1e30f;
        #pragma unroll
        for (int k = 0; k < 8; k++) {
            v[k] = logits[q * NC + lane + 32 * k];
            m = fmaxf(m, v[k]);
        }
        #pragma unroll
        for (int o = 16; o > 0; o >>= 1) m = fmaxf(m, __shfl_xor_sync(0xffffffffu, m, o));
        float sum = 0.0f;
        #pragma unroll
        for (int k = 0; k < 8; k++) sum += __expf(v[k] - m);
        #pragma unroll
        for (int o = 16; o > 0; o >>= 1) sum += __shfl_xor_sync(0xffffffffu, sum, o);
        if (lane == 0 && n < N) {
            float lse = m + __logf(sum);
            float ly  = logits[q * NC + ycls[q]];
            part[q] = lse - ly;
        }
    }
    __syncthreads();
    if (tid == 0) {
        float tot = 0.0f;
        #pragma unroll
        for (int q = 0; q < QB; q++) tot += part[q];
        atomicAdd(out, tot * (1.0f / (float)N));
    }
}

// ---------------------------------------------------------------------------
extern "C" void kernel_launch(void* const* d_in, const int* in_sizes, int n_in,
                              void* d_out, int out_size)
{
    const float* xq  = (const float*)d_in[0];
    const float* xs  = (const float*)d_in[2];
    const void*  ys  = d_in[3];
    const void*  pos = d_in[4];
    float* out = (float*)d_out;

    int N = in_sizes[1];
    int S = in_sizes[3];
    if (N > N_MAX) N = N_MAX;
    if (S > S_MAX) S = S_MAX;

    k_zero<<<1, NC>>>(out);
    k_build<<<64, 128>>>(ys, pos, S, N);
    k1_protos<<<NC, DIM>>>(xs);
    int nblk = (N + QB - 1) / QB;
    k2_loss<<<nblk, 256>>>(xq, out, N);
}